// round 17
// baseline (speedup 1.0000x reference)
#include <cuda_runtime.h>
#include <cuda_bf16.h>
#include <cstdint>
#include <stdint.h>
#include <math.h>

// ---------------------------------------------------------------------------
// GCN 3-layer. Round 16: tf32 rounding hoisted to producers (idempotent):
//  * weights pre-rounded once into tf32-valued fp32 scratch
//  * SpMM epilogues emit tf32-rounded h1/h2
//  * GEMMs skip cvt on pre-rounded operands (only GEMM1's A-path converts)
// Bit-identical math to R15 (rel_err should stay ~3.55e-4).
// ---------------------------------------------------------------------------

#define NN 50000
#define EE 800000

__device__ float g_support[NN * 128];
__device__ float g_h1[NN * 128];
__device__ float g_h2[NN * 64];
__device__ int   g_counts[NN + 1];
__device__ int   g_offsets[NN + 1];
__device__ int   g_cursor[NN];
__device__ int   g_col[EE];
__device__ float g_val[EE];
// tf32-rounded weights
__device__ float g_w1r[500 * 128];
__device__ float g_w2r[128 * 64];
__device__ float g_w3r[64 * 16];
__device__ float g_wer[64 * 64];

__device__ __forceinline__ uint32_t smem_u32(const void* p) {
    uint32_t a;
    asm("{ .reg .u64 t; cvta.to.shared.u64 t, %1; cvt.u32.u64 %0, t; }" : "=r"(a) : "l"(p));
    return a;
}
__device__ __forceinline__ uint32_t f2tf32(float x) {
    uint32_t r;
    asm("cvt.rna.tf32.f32 %0, %1;" : "=r"(r) : "f"(x));
    return r;
}
__device__ __forceinline__ float round_tf32f(float x) {
    return __uint_as_float(f2tf32(x));
}

#define MMA_TF32(c, a, b)                                                    \
    asm volatile(                                                            \
        "mma.sync.aligned.m16n8k8.row.col.f32.tf32.tf32.f32 "                \
        "{%0,%1,%2,%3}, {%4,%5,%6,%7}, {%8,%9}, {%0,%1,%2,%3};\n"            \
        : "+f"((c)[0]), "+f"((c)[1]), "+f"((c)[2]), "+f"((c)[3])             \
        : "r"((a)[0]), "r"((a)[1]), "r"((a)[2]), "r"((a)[3]),                \
          "r"((b)[0]), "r"((b)[1]))

#define CP_ASYNC16(dst, src, sz) \
    asm volatile("cp.async.cg.shared.global [%0], [%1], 16, %2;" \
                 :: "r"(dst), "l"(src), "r"(sz))
#define CP_COMMIT() asm volatile("cp.async.commit_group;" ::: "memory")

// --------------------------- weight pre-round ------------------------------

__global__ void round_weights_kernel(const float* __restrict__ W1, const float* __restrict__ W2,
                                     const float* __restrict__ W3, const float* __restrict__ We,
                                     float* __restrict__ R1, float* __restrict__ R2,
                                     float* __restrict__ R3, float* __restrict__ Re) {
    int i = blockIdx.x * blockDim.x + threadIdx.x;
    const int n1 = 500 * 128, n2 = 128 * 64, n3 = 64 * 16, ne = 64 * 64;
    if (i < n1) { R1[i] = round_tf32f(W1[i]); return; }
    i -= n1;
    if (i < n2) { R2[i] = round_tf32f(W2[i]); return; }
    i -= n2;
    if (i < n3) { R3[i] = round_tf32f(W3[i]); return; }
    i -= n3;
    if (i < ne) { Re[i] = round_tf32f(We[i]); }
}

// ------------------------------ CSR build ----------------------------------

__global__ void hist_kernel(const int4* __restrict__ src4, int* __restrict__ counts, int E4) {
    int i = blockIdx.x * blockDim.x + threadIdx.x;
    if (i < E4) {
        int4 v = src4[i];
        atomicAdd(&counts[v.x], 1);
        atomicAdd(&counts[v.y], 1);
        atomicAdd(&counts[v.z], 1);
        atomicAdd(&counts[v.w], 1);
    }
}

__global__ void scan_kernel(const int* __restrict__ counts, int* __restrict__ offsets, int n) {
    const int T = 1024;
    __shared__ int wsum[32];
    int tid = threadIdx.x;
    int per = (n + T - 1) / T;
    int beg = tid * per;
    int end = min(beg + per, n);
    int sum = 0;
    for (int i = beg; i < end; i++) sum += counts[i];
    int lane = tid & 31, wid = tid >> 5;
    int v = sum;
    #pragma unroll
    for (int off = 1; off < 32; off <<= 1) {
        int t2 = __shfl_up_sync(0xffffffffu, v, off);
        if (lane >= off) v += t2;
    }
    if (lane == 31) wsum[wid] = v;
    __syncthreads();
    if (wid == 0) {
        int w = wsum[lane];
        #pragma unroll
        for (int off = 1; off < 32; off <<= 1) {
            int t2 = __shfl_up_sync(0xffffffffu, w, off);
            if (lane >= off) w += t2;
        }
        wsum[lane] = w;
    }
    __syncthreads();
    int pre = v - sum + (wid > 0 ? wsum[wid - 1] : 0);
    int run = pre;
    for (int i = beg; i < end; i++) { offsets[i] = run; run += counts[i]; }
    if (end == n) offsets[n] = run;
}

__global__ void scatter_kernel(const int* __restrict__ src, const int* __restrict__ dst,
                               const float* __restrict__ ev,
                               const int* __restrict__ offsets, int* __restrict__ cursor,
                               int* __restrict__ col, float* __restrict__ val, int E) {
    int i = blockIdx.x * blockDim.x + threadIdx.x;
    if (i < E) {
        int s = src[i];
        int pos = offsets[s] + atomicAdd(&cursor[s], 1);
        col[pos] = dst[i];
        val[pos] = ev[i];
    }
}

// ------------------------------ tf32 GEMM ----------------------------------
// C[M,BN] = A[M,K] @ B[K,BN] (+bias). Single-pass tf32 m16n8k8, cp.async
// NSTAGE pipeline. CVTA/CVTB: whether operand needs tf32 rounding on read
// (false when the operand is already tf32-valued).

constexpr int tgemm_smem_bytes(int BM, int BN, int NSTAGE) {
    int SA = 32 + 4, SB = BN + 8;
    return NSTAGE * (BM * SA + 32 * SB) * 4;
}

template <int BM, int BN, int WARPS_M, int WARPS_N, int NSTAGE, bool BIAS,
          bool CVTA, bool CVTB>
__global__ void __launch_bounds__(32 * WARPS_M * WARPS_N, 2)
tf32_gemm_kernel(int M, int K,
                 const float* __restrict__ A, const float* __restrict__ B,
                 const float* __restrict__ bias, float* __restrict__ C) {
    constexpr int THREADS = 32 * WARPS_M * WARPS_N;
    constexpr int BK = 32;
    constexpr int WM = BM / WARPS_M, WN = BN / WARPS_N;
    constexpr int MT = WM / 16, NT = WN / 8;
    constexpr int SA = BK + 4;
    constexpr int SB = BN + 8;
    constexpr int A_ST = BM * SA, B_ST = BK * SB;
    constexpr int ACH = BM * BK / 4;
    constexpr int BCH = BK * BN / 4;

    extern __shared__ float smemf[];

    const int tid = threadIdx.x;
    const int warp = tid >> 5, lane = tid & 31;
    const int wm = (warp / WARPS_N) * WM;
    const int wn = (warp % WARPS_N) * WN;
    const int g = lane >> 2, t = lane & 3;
    const int row0 = blockIdx.x * BM;
    const int ntiles = (K + BK - 1) / BK;

    float acc[MT][NT][4];
    #pragma unroll
    for (int mi = 0; mi < MT; mi++)
        #pragma unroll
        for (int ni = 0; ni < NT; ni++)
            #pragma unroll
            for (int q = 0; q < 4; q++) acc[mi][ni][q] = 0.f;

    auto issue_tile = [&](int tile) {
        if (tile >= ntiles) return;
        int k0 = tile * BK;
        float* as = smemf + (tile % NSTAGE) * (A_ST + B_ST);
        float* bs = as + A_ST;
        #pragma unroll
        for (int i = tid; i < ACH; i += THREADS) {
            int r = i >> 3, q = i & 7;
            int gm = row0 + r, gk = k0 + q * 4;
            uint32_t dstp = smem_u32(as + r * SA + q * 4);
            const float* srcp = A + (long)gm * K + gk;
            int sz = (gm < M && gk + 4 <= K) ? 16 : 0;
            CP_ASYNC16(dstp, srcp, sz);
        }
        #pragma unroll
        for (int i = tid; i < BCH; i += THREADS) {
            int r = i / (BN / 4), q = i % (BN / 4);
            int gk = k0 + r;
            uint32_t dstp = smem_u32(bs + r * SB + q * 4);
            const float* srcp = B + (long)gk * BN + q * 4;
            int sz = (gk < K) ? 16 : 0;
            CP_ASYNC16(dstp, srcp, sz);
        }
    };

    #pragma unroll
    for (int s = 0; s < NSTAGE - 1; s++) { issue_tile(s); CP_COMMIT(); }

    for (int tt = 0; tt < ntiles; tt++) {
        asm volatile("cp.async.wait_group %0;" :: "n"(NSTAGE - 2) : "memory");
        __syncthreads();
        issue_tile(tt + NSTAGE - 1);
        CP_COMMIT();

        const float* as = smemf + (tt % NSTAGE) * (A_ST + B_ST);
        const float* bs = as + A_ST;

        #pragma unroll
        for (int kk = 0; kk < BK; kk += 8) {
            uint32_t fa[MT][4], fb[NT][2];
            #pragma unroll
            for (int mi = 0; mi < MT; mi++) {
                int r = wm + mi * 16 + g;
                float a0 = as[r * SA + kk + t];
                float a1 = as[(r + 8) * SA + kk + t];
                float a2 = as[r * SA + kk + t + 4];
                float a3 = as[(r + 8) * SA + kk + t + 4];
                fa[mi][0] = CVTA ? f2tf32(a0) : __float_as_uint(a0);
                fa[mi][1] = CVTA ? f2tf32(a1) : __float_as_uint(a1);
                fa[mi][2] = CVTA ? f2tf32(a2) : __float_as_uint(a2);
                fa[mi][3] = CVTA ? f2tf32(a3) : __float_as_uint(a3);
            }
            #pragma unroll
            for (int ni = 0; ni < NT; ni++) {
                int c = wn + ni * 8 + g;
                float b0 = bs[(kk + t) * SB + c];
                float b1 = bs[(kk + t + 4) * SB + c];
                fb[ni][0] = CVTB ? f2tf32(b0) : __float_as_uint(b0);
                fb[ni][1] = CVTB ? f2tf32(b1) : __float_as_uint(b1);
            }
            #pragma unroll
            for (int mi = 0; mi < MT; mi++)
                #pragma unroll
                for (int ni = 0; ni < NT; ni++)
                    MMA_TF32(acc[mi][ni], fa[mi], fb[ni]);
        }
        __syncthreads();
    }

    #pragma unroll
    for (int mi = 0; mi < MT; mi++) {
        int r = row0 + wm + mi * 16 + g;
        #pragma unroll
        for (int ni = 0; ni < NT; ni++) {
            int c = wn + ni * 8 + 2 * t;
            float bx = 0.f, by = 0.f;
            if (BIAS) { bx = bias[c]; by = bias[c + 1]; }
            if (r < M)
                *(float2*)(C + (long)r * BN + c) = make_float2(acc[mi][ni][0] + bx, acc[mi][ni][1] + by);
            if (r + 8 < M)
                *(float2*)(C + (long)(r + 8) * BN + c) = make_float2(acc[mi][ni][2] + bx, acc[mi][ni][3] + by);
        }
    }
}

// ------------------------------ CSR SpMM -----------------------------------
// epilogues emit tf32-rounded values (idempotent for downstream GEMMs)

__global__ void spmm128_kernel(const float* __restrict__ support,
                               const int* __restrict__ offsets,
                               const int* __restrict__ col,
                               const float* __restrict__ val,
                               const float* __restrict__ bias,
                               float* __restrict__ out, int n) {
    int warp = (blockIdx.x * blockDim.x + threadIdx.x) >> 5;
    int lane = threadIdx.x & 31;
    if (warp >= n) return;
    int start = offsets[warp], end = offsets[warp + 1];
    const float4* sup4 = (const float4*)support;
    float4 acc = make_float4(0.f, 0.f, 0.f, 0.f);
    int j = start;
    for (; j + 2 <= end; j += 2) {
        int c0 = col[j], c1 = col[j + 1];
        float w0 = val[j], w1 = val[j + 1];
        float4 s0 = sup4[c0 * 32 + lane];
        float4 s1 = sup4[c1 * 32 + lane];
        acc.x += w0 * s0.x + w1 * s1.x;
        acc.y += w0 * s0.y + w1 * s1.y;
        acc.z += w0 * s0.z + w1 * s1.z;
        acc.w += w0 * s0.w + w1 * s1.w;
    }
    if (j < end) {
        int c = col[j]; float w = val[j];
        float4 s = sup4[c * 32 + lane];
        acc.x += w * s.x; acc.y += w * s.y; acc.z += w * s.z; acc.w += w * s.w;
    }
    float4 bb = ((const float4*)bias)[lane];
    acc.x = round_tf32f(fmaxf(acc.x + bb.x, 0.f));
    acc.y = round_tf32f(fmaxf(acc.y + bb.y, 0.f));
    acc.z = round_tf32f(fmaxf(acc.z + bb.z, 0.f));
    acc.w = round_tf32f(fmaxf(acc.w + bb.w, 0.f));
    ((float4*)out)[warp * 32 + lane] = acc;
}

__global__ void spmm64_kernel(const float* __restrict__ support,
                              const int* __restrict__ offsets,
                              const int* __restrict__ col,
                              const float* __restrict__ val,
                              const float* __restrict__ bias,
                              float* __restrict__ out, int n) {
    int warp = (blockIdx.x * blockDim.x + threadIdx.x) >> 5;
    int lane = threadIdx.x & 31;
    if (warp >= n) return;
    int start = offsets[warp], end = offsets[warp + 1];
    const float2* sup2 = (const float2*)support;
    float2 acc = make_float2(0.f, 0.f);
    int j = start;
    for (; j + 2 <= end; j += 2) {
        int c0 = col[j], c1 = col[j + 1];
        float w0 = val[j], w1 = val[j + 1];
        float2 s0 = sup2[c0 * 32 + lane];
        float2 s1 = sup2[c1 * 32 + lane];
        acc.x += w0 * s0.x + w1 * s1.x;
        acc.y += w0 * s0.y + w1 * s1.y;
    }
    if (j < end) {
        int c = col[j]; float w = val[j];
        float2 s = sup2[c * 32 + lane];
        acc.x += w * s.x; acc.y += w * s.y;
    }
    float2 bb = ((const float2*)bias)[lane];
    acc.x = round_tf32f(fmaxf(acc.x + bb.x, 0.f));
    acc.y = round_tf32f(fmaxf(acc.y + bb.y, 0.f));
    ((float2*)out)[warp * 32 + lane] = acc;
}

__global__ void spmm16_lsm_kernel(const float* __restrict__ support,
                                  const int* __restrict__ offsets,
                                  const int* __restrict__ col,
                                  const float* __restrict__ val,
                                  const float* __restrict__ bias,
                                  float* __restrict__ out, int n) {
    int t = blockIdx.x * blockDim.x + threadIdx.x;
    int grp = t >> 4;
    int sub = t & 15;
    bool active = grp < n;
    int g2 = active ? grp : (n - 1);
    int start = offsets[g2], end = offsets[g2 + 1];
    float acc = 0.f;
    for (int j = start; j < end; j++)
        acc += val[j] * support[col[j] * 16 + sub];
    acc += bias[sub];
    float m = acc;
    #pragma unroll
    for (int off = 8; off >= 1; off >>= 1)
        m = fmaxf(m, __shfl_xor_sync(0xffffffffu, m, off, 16));
    float s = expf(acc - m);
    #pragma unroll
    for (int off = 8; off >= 1; off >>= 1)
        s += __shfl_xor_sync(0xffffffffu, s, off, 16);
    if (active) out[grp * 16 + sub] = acc - (logf(s) + m);
}

// ------------------------------ launch -------------------------------------

extern "C" void kernel_launch(void* const* d_in, const int* in_sizes, int n_in,
                              void* d_out, int out_size) {
    const float* x  = (const float*)d_in[0];
    const float* ev = (const float*)d_in[1];
    const float* W1 = (const float*)d_in[2];
    const float* b1 = (const float*)d_in[3];
    const float* W2 = (const float*)d_in[4];
    const float* b2 = (const float*)d_in[5];
    const float* W3 = (const float*)d_in[6];
    const float* b3 = (const float*)d_in[7];
    const float* We = (const float*)d_in[8];
    const float* be = (const float*)d_in[9];
    const int* esrc = (const int*)d_in[10];
    const int* edst = (const int*)d_in[11];

    const int N = NN;
    const int E = in_sizes[10];

    float* out1 = (float*)d_out;
    float* out2 = (float*)d_out + (long)N * 16;

    float *p_support, *p_h1, *p_h2, *p_val;
    float *p_w1r, *p_w2r, *p_w3r, *p_wer;
    int *p_counts, *p_offsets, *p_cursor, *p_col;
    cudaGetSymbolAddress((void**)&p_support, g_support);
    cudaGetSymbolAddress((void**)&p_h1, g_h1);
    cudaGetSymbolAddress((void**)&p_h2, g_h2);
    cudaGetSymbolAddress((void**)&p_counts, g_counts);
    cudaGetSymbolAddress((void**)&p_offsets, g_offsets);
    cudaGetSymbolAddress((void**)&p_cursor, g_cursor);
    cudaGetSymbolAddress((void**)&p_col, g_col);
    cudaGetSymbolAddress((void**)&p_val, g_val);
    cudaGetSymbolAddress((void**)&p_w1r, g_w1r);
    cudaGetSymbolAddress((void**)&p_w2r, g_w2r);
    cudaGetSymbolAddress((void**)&p_w3r, g_w3r);
    cudaGetSymbolAddress((void**)&p_wer, g_wer);

    constexpr int S1 = tgemm_smem_bytes(64, 128, 3);
    constexpr int S2 = tgemm_smem_bytes(64, 64, 3);
    constexpr int S3 = tgemm_smem_bytes(128, 16, 3);
    cudaFuncSetAttribute(tf32_gemm_kernel<64, 128, 2, 4, 3, false, true, false>,
                         cudaFuncAttributeMaxDynamicSharedMemorySize, S1);
    cudaFuncSetAttribute(tf32_gemm_kernel<64, 64, 2, 4, 3, false, false, false>,
                         cudaFuncAttributeMaxDynamicSharedMemorySize, S2);
    cudaFuncSetAttribute(tf32_gemm_kernel<64, 64, 2, 4, 3, true, false, false>,
                         cudaFuncAttributeMaxDynamicSharedMemorySize, S2);
    cudaFuncSetAttribute(tf32_gemm_kernel<128, 16, 8, 1, 3, false, false, false>,
                         cudaFuncAttributeMaxDynamicSharedMemorySize, S3);

    // ---- weight pre-round + CSR build ----
    const int WTOT = 500 * 128 + 128 * 64 + 64 * 16 + 64 * 64;
    round_weights_kernel<<<(WTOT + 255) / 256, 256>>>(W1, W2, W3, We, p_w1r, p_w2r, p_w3r, p_wer);
    cudaMemsetAsync(p_counts, 0, (N + 1) * sizeof(int), 0);
    cudaMemsetAsync(p_cursor, 0, N * sizeof(int), 0);
    hist_kernel<<<(E / 4 + 255) / 256, 256>>>((const int4*)esrc, p_counts, E / 4);
    scan_kernel<<<1, 1024>>>(p_counts, p_offsets, N);
    scatter_kernel<<<(E + 255) / 256, 256>>>(esrc, edst, ev, p_offsets, p_cursor, p_col, p_val, E);

    // ---- layer 1: support = x@W1 [N,128]; h1 = tf32(relu(agg + b1)) ----
    tf32_gemm_kernel<64, 128, 2, 4, 3, false, true, false><<<(N + 63) / 64, 256, S1>>>(
        N, 500, x, p_w1r, nullptr, p_support);
    spmm128_kernel<<<(N * 32 + 255) / 256, 256>>>(p_support, p_offsets, p_col, p_val, b1, p_h1, N);

    // ---- layer 2: support = h1@W2 [N,64]; h2 = tf32(relu(agg + b2)) ----
    tf32_gemm_kernel<64, 64, 2, 4, 3, false, false, false><<<(N + 63) / 64, 256, S2>>>(
        N, 128, p_h1, p_w2r, nullptr, p_support);
    spmm64_kernel<<<(N * 32 + 255) / 256, 256>>>(p_support, p_offsets, p_col, p_val, b2, p_h2, N);

    // ---- layer 3: support = h2@W3 [N,16]; out1 = log_softmax(agg + b3) ----
    tf32_gemm_kernel<128, 16, 8, 1, 3, false, false, false><<<(N + 127) / 128, 256, S3>>>(
        N, 64, p_h2, p_w3r, nullptr, p_support);
    spmm16_lsm_kernel<<<(N * 16 + 255) / 256, 256>>>(p_support, p_offsets, p_col, p_val, b3, out1, N);

    // ---- head 2: out2 = h2@We + be ----
    tf32_gemm_kernel<64, 64, 2, 4, 3, true, false, false><<<(N + 63) / 64, 256, S2>>>(
        N, 64, p_h2, p_wer, be, out2);
}